// round 4
// baseline (speedup 1.0000x reference)
#include <cuda_runtime.h>
#include <math.h>

#define Nn 100000
#define Ee 1600000
#define NSB 196   // ceil(Nn/512)

typedef unsigned long long ull;

// ---------------- scratch (device globals) -----------------------------------
__device__ int   g_rowptr[Nn + 1];
__device__ int   g_cursor[Nn];
__device__ int   g_colidx[Ee];
__device__ int   g_bsum[NSB];
__device__ int   g_is64;
__device__ float g_mean[(size_t)Nn * 64];   // reused as z (N x 16) in layer 3
__device__ float g_out [(size_t)Nn * 64];
__device__ float g_bnsum[64];
__device__ float g_bnsq [64];
__device__ float g_bnsc [64];
__device__ float g_bnsh [64];

// ---------------- f32x2 packed helpers ---------------------------------------
__device__ __forceinline__ ull pack2(float v) {
    ull r; asm("mov.b64 %0, {%1, %1};" : "=l"(r) : "f"(v)); return r;
}
__device__ __forceinline__ ull fma2(ull a, ull b, ull c) {
    ull d; asm("fma.rn.f32x2 %0, %1, %2, %3;" : "=l"(d) : "l"(a), "l"(b), "l"(c)); return d;
}
__device__ __forceinline__ void unpack2(ull v, float& lo, float& hi) {
    asm("mov.b64 {%0, %1}, %2;" : "=f"(lo), "=f"(hi) : "l"(v));
}

__device__ __forceinline__ int edge_at(const void* ei, long long i, int is64) {
    return is64 ? (int)__ldg(&((const long long*)ei)[i]) : __ldg(&((const int*)ei)[i]);
}

// ---------------- init: zero counts + zero BN stats + dtype detect -----------
__global__ void k_init(const void* ei) {
    int i = blockIdx.x * blockDim.x + threadIdx.x;
    if (i < Nn) g_cursor[i] = 0;
    if (blockIdx.x == 0) {
        if (threadIdx.x >= 64 && threadIdx.x < 128) {
            g_bnsum[threadIdx.x - 64] = 0.f;
            g_bnsq [threadIdx.x - 64] = 0.f;
        }
        if (threadIdx.x < 32) {
            const long long* q = (const long long*)ei;
            long long v = q[(long long)threadIdx.x * 33331];
            unsigned bad = __ballot_sync(0xffffffffu, v < 0 || v >= Nn);
            if (threadIdx.x == 0) g_is64 = (bad == 0) ? 1 : 0;
        }
    }
}

// ---------------- CSR build --------------------------------------------------
__global__ void k_hist(const void* ei) {
    int is64 = g_is64;
    long long stride = (long long)gridDim.x * blockDim.x;
    for (long long e = blockIdx.x * (long long)blockDim.x + threadIdx.x; e < Ee; e += stride) {
        int d = edge_at(ei, Ee + e, is64);
        atomicAdd(&g_cursor[d], 1);
    }
}

__global__ void k_scan1() {
    __shared__ int sh[512];
    int i = blockIdx.x * 512 + threadIdx.x;
    int v = (i < Nn) ? g_cursor[i] : 0;
    sh[threadIdx.x] = v;
    __syncthreads();
    for (int off = 1; off < 512; off <<= 1) {
        int t = (threadIdx.x >= off) ? sh[threadIdx.x - off] : 0;
        __syncthreads();
        sh[threadIdx.x] += t;
        __syncthreads();
    }
    if (i < Nn) g_rowptr[i + 1] = sh[threadIdx.x];
    if (threadIdx.x == 511) g_bsum[blockIdx.x] = sh[511];
}

__global__ void k_scan2b() {
    __shared__ int sh[256];
    int tid = threadIdx.x;
    int v = (tid < NSB) ? g_bsum[tid] : 0;
    sh[tid] = v;
    __syncthreads();
    for (int off = 1; off < 256; off <<= 1) {
        int t = (tid >= off) ? sh[tid - off] : 0;
        __syncthreads();
        sh[tid] += t;
        __syncthreads();
    }
    if (tid < NSB) g_bsum[tid] = sh[tid] - v;   // exclusive
}

// add block offsets AND initialize cursor (merged fillcur)
__global__ void k_scan3() {
    int i = blockIdx.x * blockDim.x + threadIdx.x;
    if (i < Nn) {
        int fin = g_rowptr[i + 1] + g_bsum[i >> 9];
        g_rowptr[i + 1] = fin;
        if (i + 1 < Nn) g_cursor[i + 1] = fin;
    }
    if (i == 0) { g_rowptr[0] = 0; g_cursor[0] = 0; }
}

__global__ void k_scatter(const void* ei) {
    int is64 = g_is64;
    long long stride = (long long)gridDim.x * blockDim.x;
    for (long long e = blockIdx.x * (long long)blockDim.x + threadIdx.x; e < Ee; e += stride) {
        int d = edge_at(ei, Ee + e, is64);
        int s = edge_at(ei, e,      is64);
        int pos = atomicAdd(&g_cursor[d], 1);
        g_colidx[pos] = s;
    }
}

// ---------------- mean aggregation, optional fused BN+ReLU on gathered rows --
// mode 0: read from xin (layer 1, no BN). mode 1: read from g_out with BN+ReLU.
__global__ void k_agg(const float* __restrict__ xin, int mode) {
    const float* __restrict__ p = (mode == 0) ? xin : (const float*)g_out;
    int gt = blockIdx.x * blockDim.x + threadIdx.x;
    int w = gt >> 5, lane = gt & 31;
    if (w >= Nn) return;
    float sc0 = 1.f, sc1 = 1.f, sh0 = 0.f, sh1 = 0.f;
    const bool use_bn = (mode != 0);
    if (use_bn) {
        sc0 = g_bnsc[2 * lane];     sc1 = g_bnsc[2 * lane + 1];
        sh0 = g_bnsh[2 * lane];     sh1 = g_bnsh[2 * lane + 1];
    }
    int beg = g_rowptr[w], end = g_rowptr[w + 1];
    float ax = 0.f, ay = 0.f;
    for (int e = beg; e < end; e += 32) {
        int cnt = min(32, end - e);
        int s = (lane < cnt) ? __ldg(&g_colidx[e + lane]) : 0;
        int j = 0;
        for (; j + 4 <= cnt; j += 4) {
            int s0 = __shfl_sync(0xffffffffu, s, j);
            int s1 = __shfl_sync(0xffffffffu, s, j + 1);
            int s2 = __shfl_sync(0xffffffffu, s, j + 2);
            int s3 = __shfl_sync(0xffffffffu, s, j + 3);
            float2 v0 = __ldg((const float2*)(p + (size_t)s0 * 64) + lane);
            float2 v1 = __ldg((const float2*)(p + (size_t)s1 * 64) + lane);
            float2 v2 = __ldg((const float2*)(p + (size_t)s2 * 64) + lane);
            float2 v3 = __ldg((const float2*)(p + (size_t)s3 * 64) + lane);
            if (use_bn) {
                v0.x = fmaxf(fmaf(v0.x, sc0, sh0), 0.f); v0.y = fmaxf(fmaf(v0.y, sc1, sh1), 0.f);
                v1.x = fmaxf(fmaf(v1.x, sc0, sh0), 0.f); v1.y = fmaxf(fmaf(v1.y, sc1, sh1), 0.f);
                v2.x = fmaxf(fmaf(v2.x, sc0, sh0), 0.f); v2.y = fmaxf(fmaf(v2.y, sc1, sh1), 0.f);
                v3.x = fmaxf(fmaf(v3.x, sc0, sh0), 0.f); v3.y = fmaxf(fmaf(v3.y, sc1, sh1), 0.f);
            }
            ax += v0.x + v1.x + v2.x + v3.x;
            ay += v0.y + v1.y + v2.y + v3.y;
        }
        for (; j < cnt; j++) {
            int sj = __shfl_sync(0xffffffffu, s, j);
            float2 v = __ldg((const float2*)(p + (size_t)sj * 64) + lane);
            if (use_bn) {
                v.x = fmaxf(fmaf(v.x, sc0, sh0), 0.f);
                v.y = fmaxf(fmaf(v.y, sc1, sh1), 0.f);
            }
            ax += v.x; ay += v.y;
        }
    }
    float inv = 1.0f / (float)max(end - beg, 1);
    ((float2*)g_mean)[(size_t)w * 32 + lane] = make_float2(ax * inv, ay * inv);
}

// ---------------- fused dual-GEMM (64->64, f32x2) + L2 normalize -------------
// mode 0: own-row from xin (no BN). mode 1: own-row from g_out with BN+ReLU.
// Writes g_out (safe for mode 1: each thread reads row r before writing row r).
__global__ void __launch_bounds__(256) k_gemm64(const float* __restrict__ xin, int mode,
                                                const float* __restrict__ Wl,
                                                const float* __restrict__ Wr,
                                                const float* __restrict__ b) {
    __shared__ __align__(16) float sWl[64 * 64];   // sWl[k*64 + j] = Wl[j][k]
    __shared__ __align__(16) float sWr[64 * 64];
    __shared__ __align__(16) float sb[64];
    __shared__ float sSc[64], sSh[64];
    const bool use_bn = (mode != 0);
    for (int i = threadIdx.x; i < 64 * 64; i += 256) {
        int j = i >> 6, k = i & 63;
        sWl[k * 64 + j] = Wl[i];
        sWr[k * 64 + j] = Wr[i];
    }
    if (threadIdx.x < 64) {
        sb[threadIdx.x] = b[threadIdx.x];
        sSc[threadIdx.x] = use_bn ? g_bnsc[threadIdx.x] : 1.f;
        sSh[threadIdx.x] = use_bn ? g_bnsh[threadIdx.x] : 0.f;
    }
    __syncthreads();

    const float* __restrict__ hp = (mode == 0) ? xin : (const float*)g_out;
    int r = blockIdx.x * 256 + threadIdx.x;
    if (r >= Nn) return;

    ull acc[32];
    const ull* sb2 = (const ull*)sb;
    #pragma unroll
    for (int j2 = 0; j2 < 32; j2++) acc[j2] = sb2[j2];

    const float4* m4 = (const float4*)(g_mean + (size_t)r * 64);
    const float4* h4 = (const float4*)(hp + (size_t)r * 64);
    #pragma unroll 1
    for (int k4 = 0; k4 < 16; k4++) {
        float4 m = __ldg(m4 + k4), h = __ldg(h4 + k4);
        if (use_bn) {
            h.x = fmaxf(fmaf(h.x, sSc[k4 * 4 + 0], sSh[k4 * 4 + 0]), 0.f);
            h.y = fmaxf(fmaf(h.y, sSc[k4 * 4 + 1], sSh[k4 * 4 + 1]), 0.f);
            h.z = fmaxf(fmaf(h.z, sSc[k4 * 4 + 2], sSh[k4 * 4 + 2]), 0.f);
            h.w = fmaxf(fmaf(h.w, sSc[k4 * 4 + 3], sSh[k4 * 4 + 3]), 0.f);
        }
        #pragma unroll
        for (int kk = 0; kk < 4; kk++) {
            float mv = kk == 0 ? m.x : kk == 1 ? m.y : kk == 2 ? m.z : m.w;
            float hv = kk == 0 ? h.x : kk == 1 ? h.y : kk == 2 ? h.z : h.w;
            ull mv2 = pack2(mv), hv2 = pack2(hv);
            int k = k4 * 4 + kk;
            const ulonglong2* wl2 = (const ulonglong2*)(sWl + k * 64);
            const ulonglong2* wr2 = (const ulonglong2*)(sWr + k * 64);
            #pragma unroll
            for (int q = 0; q < 16; q++) {
                ulonglong2 a = wl2[q], c = wr2[q];
                acc[q * 2 + 0] = fma2(mv2, a.x, acc[q * 2 + 0]);
                acc[q * 2 + 1] = fma2(mv2, a.y, acc[q * 2 + 1]);
                acc[q * 2 + 0] = fma2(hv2, c.x, acc[q * 2 + 0]);
                acc[q * 2 + 1] = fma2(hv2, c.y, acc[q * 2 + 1]);
            }
        }
    }

    float v[64];
    float s = 0.f;
    #pragma unroll
    for (int j2 = 0; j2 < 32; j2++) {
        float lo, hi;
        unpack2(acc[j2], lo, hi);
        v[j2 * 2] = lo; v[j2 * 2 + 1] = hi;
        s += lo * lo + hi * hi;
    }
    float sc = 1.0f / fmaxf(sqrtf(s), 1e-12f);
    float4* o4 = (float4*)(g_out + (size_t)r * 64);
    #pragma unroll
    for (int j4 = 0; j4 < 16; j4++)
        o4[j4] = make_float4(v[j4 * 4] * sc, v[j4 * 4 + 1] * sc,
                             v[j4 * 4 + 2] * sc, v[j4 * 4 + 3] * sc);
}

// ---------------- batchnorm stats (vectorized) + finalize ---------------------
__global__ void k_bnstats() {
    int tid = blockIdx.x * blockDim.x + threadIdx.x;
    long long stride4 = (long long)gridDim.x * blockDim.x;  // float4 units; *4 is mult of 64
    int col = (tid * 4) & 63;
    float4 s = make_float4(0.f, 0.f, 0.f, 0.f), q = make_float4(0.f, 0.f, 0.f, 0.f);
    const float4* p = (const float4*)g_out;
    for (long long i = tid; i < (long long)Nn * 16; i += stride4) {
        float4 x = p[i];
        s.x += x.x; s.y += x.y; s.z += x.z; s.w += x.w;
        q.x += x.x * x.x; q.y += x.y * x.y; q.z += x.z * x.z; q.w += x.w * x.w;
    }
    atomicAdd(&g_bnsum[col + 0], s.x); atomicAdd(&g_bnsq[col + 0], q.x);
    atomicAdd(&g_bnsum[col + 1], s.y); atomicAdd(&g_bnsq[col + 1], q.y);
    atomicAdd(&g_bnsum[col + 2], s.z); atomicAdd(&g_bnsq[col + 2], q.z);
    atomicAdd(&g_bnsum[col + 3], s.w); atomicAdd(&g_bnsq[col + 3], q.w);
}

// compute sc/sh, then zero the stats for the next layer
__global__ void k_bnfinal(const float* __restrict__ gamma, const float* __restrict__ beta) {
    int j = threadIdx.x;
    if (j < 64) {
        float mu  = g_bnsum[j] * (1.0f / Nn);
        float var = g_bnsq[j] * (1.0f / Nn) - mu * mu;
        float sc  = rsqrtf(var + 1e-5f) * gamma[j];
        g_bnsc[j] = sc;
        g_bnsh[j] = beta[j] - mu * sc;
        g_bnsum[j] = 0.f;
        g_bnsq [j] = 0.f;
    }
}

// ---------------- layer 3: BN+ReLU inline, project, then aggregate 16-wide ---
__global__ void __launch_bounds__(256) k_proj3(const float* __restrict__ Wl,
                                               const float* __restrict__ Wr,
                                               const float* __restrict__ b,
                                               float* __restrict__ out) {
    __shared__ float sWl[64 * 10];
    __shared__ float sWr[64 * 10];
    __shared__ float sb[10];
    __shared__ float sSc[64], sSh[64];
    for (int i = threadIdx.x; i < 640; i += 256) {
        int j = i / 64, k = i % 64;
        sWl[k * 10 + j] = Wl[i];
        sWr[k * 10 + j] = Wr[i];
    }
    if (threadIdx.x < 10) sb[threadIdx.x] = b[threadIdx.x];
    if (threadIdx.x < 64) { sSc[threadIdx.x] = g_bnsc[threadIdx.x]; sSh[threadIdx.x] = g_bnsh[threadIdx.x]; }
    __syncthreads();

    int r = blockIdx.x * 256 + threadIdx.x;
    if (r >= Nn) return;

    float al[10], ar[10];
    #pragma unroll
    for (int j = 0; j < 10; j++) { al[j] = 0.f; ar[j] = sb[j]; }

    const float4* h4 = (const float4*)(g_out + (size_t)r * 64);
    #pragma unroll 1
    for (int k4 = 0; k4 < 16; k4++) {
        float4 h = __ldg(h4 + k4);
        h.x = fmaxf(fmaf(h.x, sSc[k4 * 4 + 0], sSh[k4 * 4 + 0]), 0.f);
        h.y = fmaxf(fmaf(h.y, sSc[k4 * 4 + 1], sSh[k4 * 4 + 1]), 0.f);
        h.z = fmaxf(fmaf(h.z, sSc[k4 * 4 + 2], sSh[k4 * 4 + 2]), 0.f);
        h.w = fmaxf(fmaf(h.w, sSc[k4 * 4 + 3], sSh[k4 * 4 + 3]), 0.f);
        #pragma unroll
        for (int kk = 0; kk < 4; kk++) {
            float hv = kk == 0 ? h.x : kk == 1 ? h.y : kk == 2 ? h.z : h.w;
            int k = k4 * 4 + kk;
            #pragma unroll
            for (int j = 0; j < 10; j++) {
                al[j] += hv * sWl[k * 10 + j];
                ar[j] += hv * sWr[k * 10 + j];
            }
        }
    }
    float* z = g_mean + (size_t)r * 16;
    #pragma unroll
    for (int j = 0; j < 10; j++) z[j] = al[j];
    #pragma unroll
    for (int j = 10; j < 16; j++) z[j] = 0.f;
    #pragma unroll
    for (int j = 0; j < 10; j++) out[(size_t)r * 10 + j] = ar[j];
}

__global__ void k_agg10(float* __restrict__ out) {
    int gt = blockIdx.x * blockDim.x + threadIdx.x;
    int w = gt >> 5, lane = gt & 31;
    if (w >= Nn) return;
    int beg = g_rowptr[w], end = g_rowptr[w + 1];
    int half = lane >> 4, col = lane & 15;
    float a = 0.f;
    for (int e = beg + half; e < end; e += 2) {
        int s = __ldg(&g_colidx[e]);
        a += __ldg(&g_mean[(size_t)s * 16 + col]);
    }
    a += __shfl_down_sync(0xffffffffu, a, 16);
    if (lane < 10) {
        float inv = 1.0f / (float)max(end - beg, 1);
        out[(size_t)w * 10 + lane] += a * inv;
    }
}

// ---------------- launch -----------------------------------------------------
extern "C" void kernel_launch(void* const* d_in, const int* in_sizes, int n_in,
                              void* d_out, int out_size) {
    const float* x   = (const float*)d_in[0];
    const void*  ei  = d_in[1];
    const float* Wl1 = (const float*)d_in[2];
    const float* Wr1 = (const float*)d_in[3];
    const float* b1  = (const float*)d_in[4];
    const float* g1  = (const float*)d_in[5];
    const float* be1 = (const float*)d_in[6];
    const float* Wl2 = (const float*)d_in[7];
    const float* Wr2 = (const float*)d_in[8];
    const float* b2  = (const float*)d_in[9];
    const float* g2  = (const float*)d_in[10];
    const float* be2 = (const float*)d_in[11];
    const float* Wl3 = (const float*)d_in[12];
    const float* Wr3 = (const float*)d_in[13];
    const float* b3  = (const float*)d_in[14];
    float* out = (float*)d_out;

    const int NBLK_N   = (Nn + 255) / 256;      // 391
    const int NBLK_AGG = (Nn * 32 + 255) / 256; // 12500
    const int NBLK_E   = 2048;
    const int NBLK_EW  = 592;

    // CSR build (6 launches)
    k_init   <<<NBLK_N, 256>>>(ei);
    k_hist   <<<NBLK_E, 256>>>(ei);
    k_scan1  <<<NSB, 512>>>();
    k_scan2b <<<1, 256>>>();
    k_scan3  <<<NBLK_N, 256>>>();
    k_scatter<<<NBLK_E, 256>>>(ei);

    // Layer 1 (inputs from x, no BN)
    k_agg    <<<NBLK_AGG, 256>>>(x, 0);
    k_gemm64 <<<NBLK_N, 256>>>(x, 0, Wl1, Wr1, b1);
    k_bnstats<<<NBLK_EW, 256>>>();
    k_bnfinal<<<1, 64>>>(g1, be1);

    // Layer 2 (inputs from g_out selected IN-KERNEL, BN1+ReLU fused)
    k_agg    <<<NBLK_AGG, 256>>>(nullptr, 1);
    k_gemm64 <<<NBLK_N, 256>>>(nullptr, 1, Wl2, Wr2, b2);
    k_bnstats<<<NBLK_EW, 256>>>();
    k_bnfinal<<<1, 64>>>(g2, be2);

    // Layer 3 (BN2+ReLU fused into projection; project-then-aggregate)
    k_proj3  <<<NBLK_N, 256>>>(Wl3, Wr3, b3, out);
    k_agg10  <<<NBLK_AGG, 256>>>(out);
}